// round 16
// baseline (speedup 1.0000x reference)
#include <cuda_runtime.h>
#include <cuda_fp16.h>
#include <cstdint>
#include <cstddef>

// ---------------- problem dims ----------------
#define S_LEN  2048
#define BATCH  2
#define DMODEL 4096
#define NHQ    32
#define NKV    8
#define HDIM   128
#define N_QKV  ((NHQ + 2*NKV)*HDIM)   // 6144
#define MROWS  (S_LEN*BATCH)          // 4096
#define KG16   (DMODEL/16)            // 256
#define NSM    148
#define GRID_P (3*NSM)                // persistent grid (3 CTAs/SM)

// ---------------- scratch (device globals) ----------------
__device__ __half g_hid2h [(size_t)MROWS*DMODEL];
__device__ __half g_attn2h[(size_t)MROWS*DMODEL];
__device__ __half g_Wq2h[(size_t)DMODEL*N_QKV];
__device__ __half g_Wo2h[(size_t)DMODEL*DMODEL];
// Q A-frag layout: (((bh*128+sb)*8 + kk)*32 + lane)*8 + (rs+2cs)*2 + lo
__device__ __half g_Q2h[(size_t)BATCH*NHQ*S_LEN*HDIM];
// K pair layout (pairs over d):  ((bhk*8+ds)*2048 + s)*16 + t2*2 + lo
__device__ __half g_K2h[(size_t)BATCH*NKV*S_LEN*HDIM];
// V pair layout (pairs over s):  ((bhk*128+kg)*128 + d)*16 + t2*2 + lo
__device__ __half g_V2h[(size_t)BATCH*NKV*S_LEN*HDIM];

// ---------------- helpers ----------------
__device__ __forceinline__ uint32_t f2h2(float lo, float hi) {
    __half2 h = __floats2half2_rn(lo, hi);   // .x = lo half
    return *reinterpret_cast<uint32_t*>(&h);
}
__device__ __forceinline__ void mma_f16(float* c, const uint32_t* a, const uint32_t* b) {
    asm volatile(
        "mma.sync.aligned.m16n8k16.row.col.f32.f16.f16.f32 "
        "{%0,%1,%2,%3},{%4,%5,%6,%7},{%8,%9},{%0,%1,%2,%3};"
        : "+f"(c[0]), "+f"(c[1]), "+f"(c[2]), "+f"(c[3])
        : "r"(a[0]), "r"(a[1]), "r"(a[2]), "r"(a[3]), "r"(b[0]), "r"(b[1]));
}
__device__ __forceinline__ uint32_t s2u(const void* p) {
    return (uint32_t)__cvta_generic_to_shared(p);
}
__device__ __forceinline__ void cp16(uint32_t s, const void* g) {
    asm volatile("cp.async.cg.shared.global [%0], [%1], 16;" :: "r"(s), "l"(g));
}
__device__ __forceinline__ void cp_commit() { asm volatile("cp.async.commit_group;"); }
__device__ __forceinline__ void cp_wait0() { asm volatile("cp.async.wait_group 0;"); }
__device__ __forceinline__ void cp_wait1() { asm volatile("cp.async.wait_group 1;"); }
__device__ __forceinline__ float ex2a(float x) {
    float y; asm("ex2.approx.ftz.f32 %0, %1;" : "=f"(y) : "f"(x)); return y;
}

#define NEG_INF __int_as_float(0xff800000)
// 1/sqrt(128) * log2(e)  — softmax runs in log2 domain (ex2 instead of exp)
#define QSCALE_LOG2E 0.12751744154070513f

// =====================================================================
// Prepass 1: hidden [4096 x 4096] fp32 -> A-fragment fp16 layout
// =====================================================================
__global__ __launch_bounds__(256) void pack_A_kernel(const float* __restrict__ src,
                                                     __half* __restrict__ dst) {
    __shared__ float st[16][264];
    const int tid = threadIdx.x;
    const int mb = blockIdx.y;
    const int k0 = blockIdx.x * 256;
    #pragma unroll
    for (int p = 0; p < 16; p++) {
        int j = tid + p*256;
        int row = j >> 8, col = j & 255;
        st[row][col] = src[(size_t)(mb*16 + row)*DMODEL + k0 + col];
    }
    __syncthreads();
    const int kgb = k0 >> 4;
    #pragma unroll
    for (int p = 0; p < 2; p++) {
        int jb = tid + p*256;
        int kg_l = jb >> 5, lane = jb & 31;
        int gid = lane >> 2, tq = lane & 3;
        int c0 = kg_l*16 + 2*tq;
        int c1 = c0 + 8;
        uint4 o;
        o.x = f2h2(st[gid    ][c0], st[gid    ][c0+1]);
        o.y = f2h2(st[gid + 8][c0], st[gid + 8][c0+1]);
        o.z = f2h2(st[gid    ][c1], st[gid    ][c1+1]);
        o.w = f2h2(st[gid + 8][c1], st[gid + 8][c1+1]);
        *(uint4*)(dst + (((size_t)mb*KG16 + kgb + kg_l)*32 + lane)*8) = o;
    }
}

// =====================================================================
// Prepass 2: W [4096 x N] fp32 -> pair fp16 layout [kg16][n][16]
// =====================================================================
template<int N>
__global__ __launch_bounds__(256) void pack_W_kernel(const float* __restrict__ src,
                                                     __half* __restrict__ dst) {
    __shared__ float st[16][264];
    const int tid = threadIdx.x;
    const int kg = blockIdx.y;
    const int n0 = blockIdx.x * 256;
    #pragma unroll
    for (int p = 0; p < 16; p++)
        st[p][tid] = src[(size_t)(kg*16 + p)*N + n0 + tid];
    __syncthreads();
    const int n = n0 + tid;
    uint32_t h2s[8];
    #pragma unroll
    for (int j = 0; j < 8; j++) {
        int t2 = (j < 4) ? 2*j : 2*(j-4) + 1;
        h2s[t2] = f2h2(st[2*j][tid], st[2*j+1][tid]);
    }
    uint4* d = (uint4*)(dst + ((size_t)kg*N + n)*16);
    d[0] = make_uint4(h2s[0], h2s[1], h2s[2], h2s[3]);
    d[1] = make_uint4(h2s[4], h2s[5], h2s[6], h2s[7]);
}

// =====================================================================
// fp16 GEMM (R15 proven, unchanged): persistent 128-thread CTAs,
// 3 CTAs/SM, CTA tile 64x128, warp 32x64, BK=64, 3-stage cp.async.
// =====================================================================
#define GSTAGE_HALF 12288                 // 24 KB per stage (halves)
#define GEMM_SMEM (3*GSTAGE_HALF*2)       // 73728 B
#define SROW 136                          // staging row stride in halves

template<int N, int MODE>
__global__ __launch_bounds__(128, 3)
void gemm_h_kernel(const __half* __restrict__ Ah,
                   const __half* __restrict__ Wh,
                   float* __restrict__ C) {
    constexpr int KT  = DMODEL / 64;     // 64
    constexpr int NBN = N / 128;
    constexpr int NT  = (MROWS/64) * NBN;

    extern __shared__ __half sh[];

    const int tid  = threadIdx.x;
    const int wid  = tid >> 5, lane = tid & 31;
    const int gid  = lane >> 2, tig = lane & 3;
    const int wrow = wid >> 1, wcol = wid & 1;   // warp grid 2(M) x 2(N)

    for (int t = blockIdx.x; t < NT; t += gridDim.x) {
        const int bm = t / NBN, bn = t - bm*NBN;   // bm in 64-row units

        auto load_stage = [&](int kt) {
            __half* base = sh + (kt % 3)*GSTAGE_HALF;
            #pragma unroll
            for (int p = 0; p < 4; p++) {            // A: 512 chunks (64 rows)
                int j = tid + p*128;
                int mbl = j >> 7, kgl = (j >> 5) & 3, ln = j & 31;
                cp16(s2u(base + (size_t)j*8),
                     Ah + (((size_t)(bm*4 + mbl)*KG16 + kt*4 + kgl)*32 + ln)*8);
            }
            __half* bb = base + 4096;
            #pragma unroll
            for (int p = 0; p < 8; p++) {            // B: 1024 chunks (128 cols)
                int j = tid + p*128;
                int kgl = j >> 8, r = j & 255, nl = r >> 1, hf = r & 1;
                cp16(s2u(bb + (kgl*128 + nl)*16 + hf*8),
                     Wh + ((size_t)(kt*4 + kgl)*N + bn*128 + nl)*16 + hf*8);
            }
            cp_commit();
        };

        float acc[2][8][4];
        #pragma unroll
        for (int mf = 0; mf < 2; mf++)
            #pragma unroll
            for (int nf = 0; nf < 8; nf++)
                #pragma unroll
                for (int i = 0; i < 4; i++) acc[mf][nf][i] = 0.f;

        load_stage(0);
        load_stage(1);

        for (int kt = 0; kt < KT; kt++) {
            if (kt + 2 < KT) cp_wait1(); else cp_wait0();
            __syncthreads();
            if (kt + 2 < KT) load_stage(kt + 2);

            const __half* base = sh + (kt % 3)*GSTAGE_HALF;
            const uint4* a4 = (const uint4*)base;
            const uint2* b2 = (const uint2*)(base + 4096);

            #pragma unroll
            for (int ks = 0; ks < 4; ks++) {
                uint32_t af[2][4];
                #pragma unroll
                for (int mf = 0; mf < 2; mf++) {
                    uint4 av = a4[((wrow*2 + mf)*4 + ks)*32 + lane];
                    af[mf][0] = av.x; af[mf][1] = av.y;
                    af[mf][2] = av.z; af[mf][3] = av.w;
                }
                #pragma unroll
                for (int nf = 0; nf < 8; nf++) {
                    uint2 bv = b2[(ks*128 + wcol*64 + nf*8 + gid)*4 + tig];
                    mma_f16(acc[0][nf], af[0], (const uint32_t*)&bv);
                    mma_f16(acc[1][nf], af[1], (const uint32_t*)&bv);
                }
            }
        }

        if (MODE == 1) {
            #pragma unroll
            for (int mf = 0; mf < 2; mf++) {
                #pragma unroll
                for (int nf = 0; nf < 8; nf++) {
                    int r = bm*64 + wrow*32 + mf*16 + gid;
                    int c = bn*128 + wcol*64 + nf*8 + tig*2;
                    *(float2*)&C[(size_t)r*N + c]
                        = make_float2(acc[mf][nf][0], acc[mf][nf][1]);
                    *(float2*)&C[(size_t)(r+8)*N + c]
                        = make_float2(acc[mf][nf][2], acc[mf][nf][3]);
                }
            }
            __syncthreads();
        } else {
            const float qscale = (bn < NHQ) ? QSCALE_LOG2E : 1.0f;
            __syncthreads();

            #pragma unroll
            for (int mf = 0; mf < 2; mf++) {
                #pragma unroll
                for (int nf = 0; nf < 8; nf++) {
                    int r0 = wrow*32 + mf*16 + gid;
                    int c  = wcol*64 + nf*8 + tig*2;
                    *(uint32_t*)&sh[r0*SROW + c]
                        = f2h2(acc[mf][nf][0]*qscale, acc[mf][nf][1]*qscale);
                    *(uint32_t*)&sh[(r0+8)*SROW + c]
                        = f2h2(acc[mf][nf][2]*qscale, acc[mf][nf][3]*qscale);
                }
            }
            __syncthreads();

            if (bn < NHQ) {
                #pragma unroll
                for (int it = 0; it < 8; it++) {
                    int c0 = it*4 + wid;
                    int b = c0 >> 4, sbl = (c0 >> 3) & 1, kk = c0 & 7;
                    int gq = lane >> 2, tq = lane & 3;
                    __half vals[8];
                    #pragma unroll
                    for (int e2 = 0; e2 < 4; e2++) {    // e2 = cs*2 + rs
                        int cs = e2 >> 1, rs = e2 & 1;
                        int r = 2*(sbl*16 + rs*8 + gq) + b;
                        int col = kk*16 + cs*8 + tq*2;
                        ((uint32_t*)vals)[e2] = *(uint32_t*)&sh[r*SROW + col];
                    }
                    size_t bh = (size_t)(b*NHQ + bn);
                    size_t base = (((bh*128 + (bm*2 + sbl))*8 + kk)*32 + lane)*8;
                    *(uint4*)&g_Q2h[base] = *(uint4*)vals;
                }
            } else if (bn < NHQ + NKV) {
                const int hk = bn - NHQ;
                #pragma unroll
                for (int dsi = 0; dsi < 2; dsi++) {
                    int ds = dsi*4 + wid;
                    #pragma unroll
                    for (int i = 0; i < 2; i++) {
                        int r = lane + 32*i;
                        int b = r & 1, s = bm*32 + (r >> 1);
                        __half vals[16];
                        #pragma unroll
                        for (int j = 0; j < 8; j++) {
                            int t2 = (j < 4) ? 2*j : 2*(j-4) + 1;
                            ((uint32_t*)vals)[t2] = *(uint32_t*)&sh[r*SROW + ds*16 + 2*j];
                        }
                        size_t base = (((size_t)(b*NKV + hk)*8 + ds)*S_LEN + s)*16;
                        *(uint4*)&g_K2h[base]     = *(uint4*)&vals[0];
                        *(uint4*)&g_K2h[base + 8] = *(uint4*)&vals[8];
                    }
                }
            } else {
                const int hk = bn - NHQ - NKV;
                {
                    int b = wid >> 1, kgl = wid & 1;
                    int kg = bm*2 + kgl;
                    size_t bhk = (size_t)(b*NKV + hk);
                    #pragma unroll
                    for (int i = 0; i < 4; i++) {
                        int d = i*32 + lane;
                        __half vals[16];
                        #pragma unroll
                        for (int j = 0; j < 8; j++) {
                            int t2 = (j < 4) ? 2*j : 2*(j-4) + 1;
                            int rbase = kgl*32 + 4*j + b;
                            vals[t2*2]     = sh[rbase*SROW + d];
                            vals[t2*2 + 1] = sh[(rbase + 2)*SROW + d];
                        }
                        size_t base = ((bhk*128 + kg)*128 + d)*16;
                        *(uint4*)&g_V2h[base]     = *(uint4*)&vals[0];
                        *(uint4*)&g_V2h[base + 8] = *(uint4*)&vals[8];
                    }
                }
            }
            __syncthreads();
        }
    }
}

// =====================================================================
// fp16 flash attention v4: 128-thread CTAs (4 warps x 16 q-rows,
// qtile 64), BKV=64, 3-stage cp.async (96 KB) -> 2 CTAs/SM.
// Two independent CTAs per SM decorrelate softmax/MMA phases so the
// tensor pipe stays fed while the other CTA runs MUFU/FMA.
// Grid (32, 32, 2) = 2048 CTAs = 6.92 waves (99% util).
// Base-2 softmax; paired 4-byte epilogue stores.
// =====================================================================
#define ASTAGE_HALF 16384                 // 32 KB per stage
#define ATTN_SMEM (3*ASTAGE_HALF*2)       // 98304 B

__global__ __launch_bounds__(128, 2)
void attn_kernel() {
    extern __shared__ __half sh[];

    const int tid = threadIdx.x;
    const int wid = tid >> 5, lane = tid & 31;
    const int gid = lane >> 2, tig = lane & 3;
    const int qt = blockIdx.x, h = blockIdx.y, b = blockIdx.z;
    const int hk = h >> 2;
    const int bh = b*NHQ + h, bhk = b*NKV + hk;

    // ---- Q fragments: 8 coalesced LDG.128 (pre-scaled fp16) ----
    const int sb = qt*4 + wid;
    const uint4* q4 = (const uint4*)g_Q2h + ((size_t)bh*128 + sb)*8*32 + lane;
    uint32_t qa[8][4];
    #pragma unroll
    for (int kk = 0; kk < 8; kk++) {
        uint4 qv = q4[kk*32];
        qa[kk][0] = qv.x; qa[kk][1] = qv.y; qa[kk][2] = qv.z; qa[kk][3] = qv.w;
    }

    const __half* Kg = g_K2h + (size_t)bhk*8*S_LEN*16;
    const __half* Vg = g_V2h + (size_t)bhk*128*HDIM*16;

    // stage: K [ds 8][kvl 64][16] (16 KB) then V [kg 4][d 128][16] (16 KB)
    auto loadKV = [&](int it) {
        __half* kd = sh + (it % 3)*ASTAGE_HALF;
        #pragma unroll
        for (int p = 0; p < 8; p++) {            // K: 1024 chunks
            int j = tid + p*128;
            int ds = j >> 7, r = j & 127, kvl = r >> 1, hf = r & 1;
            cp16(s2u(kd + (ds*64 + kvl)*16 + hf*8),
                 Kg + ((size_t)ds*S_LEN + it*64 + kvl)*16 + hf*8);
        }
        __half* vd = kd + 8192;
        #pragma unroll
        for (int p = 0; p < 8; p++) {            // V: 1024 chunks
            int j = tid + p*128;
            int kg = j >> 8, r = j & 255, d = r >> 1, hf = r & 1;
            cp16(s2u(vd + (kg*128 + d)*16 + hf*8),
                 Vg + ((size_t)(it*4 + kg)*HDIM + d)*16 + hf*8);
        }
        cp_commit();
    };

    float m0 = NEG_INF, m1 = NEG_INF, l0 = 0.f, l1 = 0.f;
    float o[16][4];
    #pragma unroll
    for (int jn = 0; jn < 16; jn++)
        #pragma unroll
        for (int i = 0; i < 4; i++) o[jn][i] = 0.f;

    loadKV(0); loadKV(1);

    const int NIT = S_LEN / 64;   // 32
    for (int it = 0; it < NIT; it++) {
        if (it + 1 < NIT) cp_wait1(); else cp_wait0();
        __syncthreads();
        if (it + 2 < NIT) loadKV(it + 2);

        const __half* base = sh + (it % 3)*ASTAGE_HALF;
        const uint2* kb = (const uint2*)base;
        const uint2* vb = (const uint2*)(base + 8192);

        // ---- S = Q K^T (log2 domain; scale folded into Q) ----
        float sc[8][4];
        #pragma unroll
        for (int jn = 0; jn < 8; jn++)
            #pragma unroll
            for (int i = 0; i < 4; i++) sc[jn][i] = 0.f;

        #pragma unroll
        for (int ks = 0; ks < 8; ks++) {
            #pragma unroll
            for (int jn = 0; jn < 8; jn++) {
                uint2 kv = kb[(ks*64 + jn*8 + gid)*4 + tig];
                mma_f16(sc[jn], qa[ks], (const uint32_t*)&kv);
            }
        }

        // ---- online softmax (base-2; quad reductions) ----
        float rmax0 = NEG_INF, rmax1 = NEG_INF;
        #pragma unroll
        for (int jn = 0; jn < 8; jn++) {
            rmax0 = fmaxf(rmax0, fmaxf(sc[jn][0], sc[jn][1]));
            rmax1 = fmaxf(rmax1, fmaxf(sc[jn][2], sc[jn][3]));
        }
        rmax0 = fmaxf(rmax0, __shfl_xor_sync(0xffffffffu, rmax0, 1));
        rmax0 = fmaxf(rmax0, __shfl_xor_sync(0xffffffffu, rmax0, 2));
        rmax1 = fmaxf(rmax1, __shfl_xor_sync(0xffffffffu, rmax1, 1));
        rmax1 = fmaxf(rmax1, __shfl_xor_sync(0xffffffffu, rmax1, 2));

        float mn0 = fmaxf(m0, rmax0), mn1 = fmaxf(m1, rmax1);
        float al0 = ex2a(m0 - mn0), al1 = ex2a(m1 - mn1);

        float rs0 = 0.f, rs1 = 0.f;
        #pragma unroll
        for (int jn = 0; jn < 8; jn++) {
            sc[jn][0] = ex2a(sc[jn][0] - mn0);
            sc[jn][1] = ex2a(sc[jn][1] - mn0);
            sc[jn][2] = ex2a(sc[jn][2] - mn1);
            sc[jn][3] = ex2a(sc[jn][3] - mn1);
            rs0 += sc[jn][0] + sc[jn][1];
            rs1 += sc[jn][2] + sc[jn][3];
        }
        rs0 += __shfl_xor_sync(0xffffffffu, rs0, 1);
        rs0 += __shfl_xor_sync(0xffffffffu, rs0, 2);
        rs1 += __shfl_xor_sync(0xffffffffu, rs1, 1);
        rs1 += __shfl_xor_sync(0xffffffffu, rs1, 2);

        l0 = l0*al0 + rs0;  l1 = l1*al1 + rs1;
        m0 = mn0;           m1 = mn1;

        #pragma unroll
        for (int jn = 0; jn < 16; jn++) {
            o[jn][0] *= al0; o[jn][1] *= al0;
            o[jn][2] *= al1; o[jn][3] *= al1;
        }

        // ---- O += P V : C-frag of S == A-frag halves of P ----
        #pragma unroll
        for (int g = 0; g < 4; g++) {
            uint32_t pa[4];
            pa[0] = f2h2(sc[2*g  ][0], sc[2*g  ][1]);
            pa[1] = f2h2(sc[2*g  ][2], sc[2*g  ][3]);
            pa[2] = f2h2(sc[2*g+1][0], sc[2*g+1][1]);
            pa[3] = f2h2(sc[2*g+1][2], sc[2*g+1][3]);
            #pragma unroll
            for (int jn = 0; jn < 16; jn++) {
                uint2 vv = vb[(g*128 + jn*8 + gid)*4 + tig];
                mma_f16(o[jn], pa, (const uint32_t*)&vv);
            }
        }
    }

    // ---- epilogue: fp16 A-fragment scatter, 4-byte paired stores ----
    float il0 = 1.f / l0, il1 = 1.f / l1;
    const int s0r = qt*64 + wid*16 + gid;
    const int m  = 2*s0r + b;
    const int mb0 = m >> 4, ml = m & 15, gA = ml & 7, rsA = ml >> 3;
    #pragma unroll
    for (int jn = 0; jn < 16; jn++) {
        int c0 = h*HDIM + jn*8 + tig*2;
        int kg = c0 >> 4, kl = c0 & 15, csA = kl >> 3, tA = (kl & 7) >> 1;
        size_t idx0 = (((size_t)mb0*KG16 + kg)*32 + gA*4 + tA)*8 + (rsA + 2*csA)*2;
        *(uint32_t*)&g_attn2h[idx0] = f2h2(o[jn][0]*il0, o[jn][1]*il0);
        *(uint32_t*)&g_attn2h[idx0 + (size_t)KG16*256]
            = f2h2(o[jn][2]*il1, o[jn][3]*il1);
    }
}

// =====================================================================
// launcher
// =====================================================================
extern "C" void kernel_launch(void* const* d_in, const int* in_sizes, int n_in,
                              void* d_out, int out_size) {
    const float* hidden = (const float*)d_in[0];
    const float* w_qkv  = (const float*)d_in[1];
    const float* w_o    = (const float*)d_in[2];
    float* out = (float*)d_out;

    cudaFuncSetAttribute(gemm_h_kernel<N_QKV,0>,
                         cudaFuncAttributeMaxDynamicSharedMemorySize, GEMM_SMEM);
    cudaFuncSetAttribute(gemm_h_kernel<DMODEL,1>,
                         cudaFuncAttributeMaxDynamicSharedMemorySize, GEMM_SMEM);
    cudaFuncSetAttribute(attn_kernel,
                         cudaFuncAttributeMaxDynamicSharedMemorySize, ATTN_SMEM);

    __half* hid2h;  cudaGetSymbolAddress((void**)&hid2h, g_hid2h);
    __half* wq2h;   cudaGetSymbolAddress((void**)&wq2h,  g_Wq2h);
    __half* wo2h;   cudaGetSymbolAddress((void**)&wo2h,  g_Wo2h);
    __half* at2h;   cudaGetSymbolAddress((void**)&at2h,  g_attn2h);

    // 0) prepasses: fp32 -> fp16 fragment/pair layouts
    pack_A_kernel<<<dim3(16, 256), 256>>>(hidden, hid2h);
    pack_W_kernel<N_QKV><<<dim3(N_QKV/256, KG16), 256>>>(w_qkv, wq2h);
    pack_W_kernel<DMODEL><<<dim3(DMODEL/256, KG16), 256>>>(w_o, wo2h);

    // 1) fused QKV projection (persistent, 3 CTAs/SM), scatter epilogue
    gemm_h_kernel<N_QKV,0><<<GRID_P, 128, GEMM_SMEM>>>(hid2h, wq2h, nullptr);

    // 2) flash attention (qtile 64, 2 CTAs/SM for phase decorrelation)
    attn_kernel<<<dim3(S_LEN/64, NHQ, BATCH), 128, ATTN_SMEM>>>();

    // 3) output projection (persistent, 3 CTAs/SM)
    gemm_h_kernel<DMODEL,1><<<GRID_P, 128, GEMM_SMEM>>>(at2h, wo2h, out);
}

// round 17
// speedup vs baseline: 1.0250x; 1.0250x over previous
#include <cuda_runtime.h>
#include <cuda_fp16.h>
#include <cstdint>
#include <cstddef>

// ---------------- problem dims ----------------
#define S_LEN  2048
#define BATCH  2
#define DMODEL 4096
#define NHQ    32
#define NKV    8
#define HDIM   128
#define N_QKV  ((NHQ + 2*NKV)*HDIM)   // 6144
#define MROWS  (S_LEN*BATCH)          // 4096
#define KG16   (DMODEL/16)            // 256
#define NSM    148
#define GRID_P (3*NSM)                // persistent grid (3 CTAs/SM)

// ---------------- scratch (device globals) ----------------
__device__ __half g_hid2h [(size_t)MROWS*DMODEL];
__device__ __half g_attn2h[(size_t)MROWS*DMODEL];
__device__ __half g_Wq2h[(size_t)DMODEL*N_QKV];
__device__ __half g_Wo2h[(size_t)DMODEL*DMODEL];
// Q A-frag layout: (((bh*128+sb)*8 + kk)*32 + lane)*8 + (rs+2cs)*2 + lo
__device__ __half g_Q2h[(size_t)BATCH*NHQ*S_LEN*HDIM];
// K pair layout (pairs over d):  ((bhk*8+ds)*2048 + s)*16 + t2*2 + lo
__device__ __half g_K2h[(size_t)BATCH*NKV*S_LEN*HDIM];
// V pair layout (pairs over s):  ((bhk*128+kg)*128 + d)*16 + t2*2 + lo
__device__ __half g_V2h[(size_t)BATCH*NKV*S_LEN*HDIM];

// ---------------- helpers ----------------
__device__ __forceinline__ uint32_t f2h2(float lo, float hi) {
    __half2 h = __floats2half2_rn(lo, hi);   // .x = lo half
    return *reinterpret_cast<uint32_t*>(&h);
}
__device__ __forceinline__ void mma_f16(float* c, const uint32_t* a, const uint32_t* b) {
    asm volatile(
        "mma.sync.aligned.m16n8k16.row.col.f32.f16.f16.f32 "
        "{%0,%1,%2,%3},{%4,%5,%6,%7},{%8,%9},{%0,%1,%2,%3};"
        : "+f"(c[0]), "+f"(c[1]), "+f"(c[2]), "+f"(c[3])
        : "r"(a[0]), "r"(a[1]), "r"(a[2]), "r"(a[3]), "r"(b[0]), "r"(b[1]));
}
__device__ __forceinline__ uint32_t s2u(const void* p) {
    return (uint32_t)__cvta_generic_to_shared(p);
}
__device__ __forceinline__ void cp16(uint32_t s, const void* g) {
    asm volatile("cp.async.cg.shared.global [%0], [%1], 16;" :: "r"(s), "l"(g));
}
__device__ __forceinline__ void cp_commit() { asm volatile("cp.async.commit_group;"); }
__device__ __forceinline__ void cp_wait0() { asm volatile("cp.async.wait_group 0;"); }
__device__ __forceinline__ void cp_wait1() { asm volatile("cp.async.wait_group 1;"); }
__device__ __forceinline__ float ex2a(float x) {
    float y; asm("ex2.approx.ftz.f32 %0, %1;" : "=f"(y) : "f"(x)); return y;
}

#define NEG_INF __int_as_float(0xff800000)
// 1/sqrt(128) * log2(e)  — softmax runs in log2 domain (ex2 instead of exp)
#define QSCALE_LOG2E 0.12751744154070513f

// =====================================================================
// Fused prepass: one launch does all three packs.
//   blocks [0, 4096):        hidden -> A-fragment fp16  (16 x 256 grid)
//   blocks [4096, 10240):    w_qkv  -> pair fp16        (24 x 256 grid)
//   blocks [10240, 14336):   w_o    -> pair fp16        (16 x 256 grid)
// =====================================================================
__device__ __forceinline__ void pack_A_body(const float* __restrict__ src,
                                            __half* __restrict__ dst,
                                            int bx, int by, int tid,
                                            float st[16][264]) {
    const int mb = by;
    const int k0 = bx * 256;
    #pragma unroll
    for (int p = 0; p < 16; p++) {
        int j = tid + p*256;
        int row = j >> 8, col = j & 255;
        st[row][col] = src[(size_t)(mb*16 + row)*DMODEL + k0 + col];
    }
    __syncthreads();
    const int kgb = k0 >> 4;
    #pragma unroll
    for (int p = 0; p < 2; p++) {
        int jb = tid + p*256;
        int kg_l = jb >> 5, lane = jb & 31;
        int gid = lane >> 2, tq = lane & 3;
        int c0 = kg_l*16 + 2*tq;
        int c1 = c0 + 8;
        uint4 o;
        o.x = f2h2(st[gid    ][c0], st[gid    ][c0+1]);
        o.y = f2h2(st[gid + 8][c0], st[gid + 8][c0+1]);
        o.z = f2h2(st[gid    ][c1], st[gid    ][c1+1]);
        o.w = f2h2(st[gid + 8][c1], st[gid + 8][c1+1]);
        *(uint4*)(dst + (((size_t)mb*KG16 + kgb + kg_l)*32 + lane)*8) = o;
    }
}

__device__ __forceinline__ void pack_W_body(const float* __restrict__ src,
                                            __half* __restrict__ dst,
                                            int N, int bx, int by, int tid,
                                            float st[16][264]) {
    const int kg = by;
    const int n0 = bx * 256;
    #pragma unroll
    for (int p = 0; p < 16; p++)
        st[p][tid] = src[(size_t)(kg*16 + p)*N + n0 + tid];
    __syncthreads();
    const int n = n0 + tid;
    uint32_t h2s[8];
    #pragma unroll
    for (int j = 0; j < 8; j++) {
        int t2 = (j < 4) ? 2*j : 2*(j-4) + 1;
        h2s[t2] = f2h2(st[2*j][tid], st[2*j+1][tid]);
    }
    uint4* d = (uint4*)(dst + ((size_t)kg*N + n)*16);
    d[0] = make_uint4(h2s[0], h2s[1], h2s[2], h2s[3]);
    d[1] = make_uint4(h2s[4], h2s[5], h2s[6], h2s[7]);
}

__global__ __launch_bounds__(256) void pack_all_kernel(const float* __restrict__ hidden,
                                                       const float* __restrict__ w_qkv,
                                                       const float* __restrict__ w_o) {
    __shared__ float st[16][264];
    const int tid = threadIdx.x;
    const int blk = blockIdx.x;
    if (blk < 4096) {
        // pack_A: original grid (16, 256)
        pack_A_body(hidden, g_hid2h, blk & 15, blk >> 4, tid, st);
    } else if (blk < 4096 + 6144) {
        // pack_W<6144>: original grid (24, 256)
        int j = blk - 4096;
        pack_W_body(w_qkv, g_Wq2h, N_QKV, j % 24, j / 24, tid, st);
    } else {
        // pack_W<4096>: original grid (16, 256)
        int j = blk - 4096 - 6144;
        pack_W_body(w_o, g_Wo2h, DMODEL, j & 15, j >> 4, tid, st);
    }
}

// =====================================================================
// fp16 GEMM (R15 proven, unchanged): persistent 128-thread CTAs,
// 3 CTAs/SM, CTA tile 64x128, warp 32x64, BK=64, 3-stage cp.async.
// =====================================================================
#define GSTAGE_HALF 12288                 // 24 KB per stage (halves)
#define GEMM_SMEM (3*GSTAGE_HALF*2)       // 73728 B
#define SROW 136                          // staging row stride in halves

template<int N, int MODE>
__global__ __launch_bounds__(128, 3)
void gemm_h_kernel(const __half* __restrict__ Ah,
                   const __half* __restrict__ Wh,
                   float* __restrict__ C) {
    constexpr int KT  = DMODEL / 64;     // 64
    constexpr int NBN = N / 128;
    constexpr int NT  = (MROWS/64) * NBN;

    extern __shared__ __half sh[];

    const int tid  = threadIdx.x;
    const int wid  = tid >> 5, lane = tid & 31;
    const int gid  = lane >> 2, tig = lane & 3;
    const int wrow = wid >> 1, wcol = wid & 1;   // warp grid 2(M) x 2(N)

    for (int t = blockIdx.x; t < NT; t += gridDim.x) {
        const int bm = t / NBN, bn = t - bm*NBN;   // bm in 64-row units

        auto load_stage = [&](int kt) {
            __half* base = sh + (kt % 3)*GSTAGE_HALF;
            #pragma unroll
            for (int p = 0; p < 4; p++) {            // A: 512 chunks (64 rows)
                int j = tid + p*128;
                int mbl = j >> 7, kgl = (j >> 5) & 3, ln = j & 31;
                cp16(s2u(base + (size_t)j*8),
                     Ah + (((size_t)(bm*4 + mbl)*KG16 + kt*4 + kgl)*32 + ln)*8);
            }
            __half* bb = base + 4096;
            #pragma unroll
            for (int p = 0; p < 8; p++) {            // B: 1024 chunks (128 cols)
                int j = tid + p*128;
                int kgl = j >> 8, r = j & 255, nl = r >> 1, hf = r & 1;
                cp16(s2u(bb + (kgl*128 + nl)*16 + hf*8),
                     Wh + ((size_t)(kt*4 + kgl)*N + bn*128 + nl)*16 + hf*8);
            }
            cp_commit();
        };

        float acc[2][8][4];
        #pragma unroll
        for (int mf = 0; mf < 2; mf++)
            #pragma unroll
            for (int nf = 0; nf < 8; nf++)
                #pragma unroll
                for (int i = 0; i < 4; i++) acc[mf][nf][i] = 0.f;

        load_stage(0);
        load_stage(1);

        for (int kt = 0; kt < KT; kt++) {
            if (kt + 2 < KT) cp_wait1(); else cp_wait0();
            __syncthreads();
            if (kt + 2 < KT) load_stage(kt + 2);

            const __half* base = sh + (kt % 3)*GSTAGE_HALF;
            const uint4* a4 = (const uint4*)base;
            const uint2* b2 = (const uint2*)(base + 4096);

            #pragma unroll
            for (int ks = 0; ks < 4; ks++) {
                uint32_t af[2][4];
                #pragma unroll
                for (int mf = 0; mf < 2; mf++) {
                    uint4 av = a4[((wrow*2 + mf)*4 + ks)*32 + lane];
                    af[mf][0] = av.x; af[mf][1] = av.y;
                    af[mf][2] = av.z; af[mf][3] = av.w;
                }
                #pragma unroll
                for (int nf = 0; nf < 8; nf++) {
                    uint2 bv = b2[(ks*128 + wcol*64 + nf*8 + gid)*4 + tig];
                    mma_f16(acc[0][nf], af[0], (const uint32_t*)&bv);
                    mma_f16(acc[1][nf], af[1], (const uint32_t*)&bv);
                }
            }
        }

        if (MODE == 1) {
            #pragma unroll
            for (int mf = 0; mf < 2; mf++) {
                #pragma unroll
                for (int nf = 0; nf < 8; nf++) {
                    int r = bm*64 + wrow*32 + mf*16 + gid;
                    int c = bn*128 + wcol*64 + nf*8 + tig*2;
                    *(float2*)&C[(size_t)r*N + c]
                        = make_float2(acc[mf][nf][0], acc[mf][nf][1]);
                    *(float2*)&C[(size_t)(r+8)*N + c]
                        = make_float2(acc[mf][nf][2], acc[mf][nf][3]);
                }
            }
            __syncthreads();
        } else {
            const float qscale = (bn < NHQ) ? QSCALE_LOG2E : 1.0f;
            __syncthreads();

            #pragma unroll
            for (int mf = 0; mf < 2; mf++) {
                #pragma unroll
                for (int nf = 0; nf < 8; nf++) {
                    int r0 = wrow*32 + mf*16 + gid;
                    int c  = wcol*64 + nf*8 + tig*2;
                    *(uint32_t*)&sh[r0*SROW + c]
                        = f2h2(acc[mf][nf][0]*qscale, acc[mf][nf][1]*qscale);
                    *(uint32_t*)&sh[(r0+8)*SROW + c]
                        = f2h2(acc[mf][nf][2]*qscale, acc[mf][nf][3]*qscale);
                }
            }
            __syncthreads();

            if (bn < NHQ) {
                #pragma unroll
                for (int it = 0; it < 8; it++) {
                    int c0 = it*4 + wid;
                    int b = c0 >> 4, sbl = (c0 >> 3) & 1, kk = c0 & 7;
                    int gq = lane >> 2, tq = lane & 3;
                    __half vals[8];
                    #pragma unroll
                    for (int e2 = 0; e2 < 4; e2++) {    // e2 = cs*2 + rs
                        int cs = e2 >> 1, rs = e2 & 1;
                        int r = 2*(sbl*16 + rs*8 + gq) + b;
                        int col = kk*16 + cs*8 + tq*2;
                        ((uint32_t*)vals)[e2] = *(uint32_t*)&sh[r*SROW + col];
                    }
                    size_t bh = (size_t)(b*NHQ + bn);
                    size_t base = (((bh*128 + (bm*2 + sbl))*8 + kk)*32 + lane)*8;
                    *(uint4*)&g_Q2h[base] = *(uint4*)vals;
                }
            } else if (bn < NHQ + NKV) {
                const int hk = bn - NHQ;
                #pragma unroll
                for (int dsi = 0; dsi < 2; dsi++) {
                    int ds = dsi*4 + wid;
                    #pragma unroll
                    for (int i = 0; i < 2; i++) {
                        int r = lane + 32*i;
                        int b = r & 1, s = bm*32 + (r >> 1);
                        __half vals[16];
                        #pragma unroll
                        for (int j = 0; j < 8; j++) {
                            int t2 = (j < 4) ? 2*j : 2*(j-4) + 1;
                            ((uint32_t*)vals)[t2] = *(uint32_t*)&sh[r*SROW + ds*16 + 2*j];
                        }
                        size_t base = (((size_t)(b*NKV + hk)*8 + ds)*S_LEN + s)*16;
                        *(uint4*)&g_K2h[base]     = *(uint4*)&vals[0];
                        *(uint4*)&g_K2h[base + 8] = *(uint4*)&vals[8];
                    }
                }
            } else {
                const int hk = bn - NHQ - NKV;
                {
                    int b = wid >> 1, kgl = wid & 1;
                    int kg = bm*2 + kgl;
                    size_t bhk = (size_t)(b*NKV + hk);
                    #pragma unroll
                    for (int i = 0; i < 4; i++) {
                        int d = i*32 + lane;
                        __half vals[16];
                        #pragma unroll
                        for (int j = 0; j < 8; j++) {
                            int t2 = (j < 4) ? 2*j : 2*(j-4) + 1;
                            int rbase = kgl*32 + 4*j + b;
                            vals[t2*2]     = sh[rbase*SROW + d];
                            vals[t2*2 + 1] = sh[(rbase + 2)*SROW + d];
                        }
                        size_t base = ((bhk*128 + kg)*128 + d)*16;
                        *(uint4*)&g_V2h[base]     = *(uint4*)&vals[0];
                        *(uint4*)&g_V2h[base + 8] = *(uint4*)&vals[8];
                    }
                }
            }
            __syncthreads();
        }
    }
}

// =====================================================================
// fp16 flash attention (R14 proven, unchanged): 1024 CTAs, 8 warps x
// 16 q-rows, BKV=128, 3-stage cp.async (64 KB/stage). Base-2 softmax;
// epilogue uses 4-byte paired stores.
// =====================================================================
#define ASTAGE_HALF 32768                 // 64 KB per stage
#define ATTN_SMEM (3*ASTAGE_HALF*2)       // 196608 B

__global__ __launch_bounds__(256, 1)
void attn_kernel() {
    extern __shared__ __half sh[];

    const int tid = threadIdx.x;
    const int wid = tid >> 5, lane = tid & 31;
    const int gid = lane >> 2, tig = lane & 3;
    const int qt = blockIdx.x, h = blockIdx.y, b = blockIdx.z;
    const int hk = h >> 2;
    const int bh = b*NHQ + h, bhk = b*NKV + hk;

    // ---- Q fragments: 8 coalesced LDG.128 (pre-scaled fp16) ----
    const int sb = qt*8 + wid;
    const uint4* q4 = (const uint4*)g_Q2h + ((size_t)bh*128 + sb)*8*32 + lane;
    uint32_t qa[8][4];
    #pragma unroll
    for (int kk = 0; kk < 8; kk++) {
        uint4 qv = q4[kk*32];
        qa[kk][0] = qv.x; qa[kk][1] = qv.y; qa[kk][2] = qv.z; qa[kk][3] = qv.w;
    }

    const __half* Kg = g_K2h + (size_t)bhk*8*S_LEN*16;
    const __half* Vg = g_V2h + (size_t)bhk*128*HDIM*16;

    // stage: K [ds 8][kvl 128][16] (32 KB) then V [kgl 8][d 128][16] (32 KB)
    auto loadKV = [&](int it) {
        __half* kd = sh + (it % 3)*ASTAGE_HALF;
        #pragma unroll
        for (int p = 0; p < 8; p++) {            // K: 2048 chunks
            int j = tid + p*256;
            int ds = j >> 8, r = j & 255, kvl = r >> 1, hf = r & 1;
            cp16(s2u(kd + (ds*128 + kvl)*16 + hf*8),
                 Kg + ((size_t)ds*S_LEN + it*128 + kvl)*16 + hf*8);
        }
        __half* vd = kd + 16384;
        #pragma unroll
        for (int p = 0; p < 8; p++) {            // V: 2048 chunks
            int j = tid + p*256;
            int kgl = j >> 8, r = j & 255, d = r >> 1, hf = r & 1;
            cp16(s2u(vd + (kgl*128 + d)*16 + hf*8),
                 Vg + ((size_t)(it*8 + kgl)*HDIM + d)*16 + hf*8);
        }
        cp_commit();
    };

    float m0 = NEG_INF, m1 = NEG_INF, l0 = 0.f, l1 = 0.f;
    float o[16][4];
    #pragma unroll
    for (int jn = 0; jn < 16; jn++)
        #pragma unroll
        for (int i = 0; i < 4; i++) o[jn][i] = 0.f;

    loadKV(0); loadKV(1);

    const int NIT = S_LEN / 128;   // 16
    for (int it = 0; it < NIT; it++) {
        if (it + 1 < NIT) cp_wait1(); else cp_wait0();
        __syncthreads();
        if (it + 2 < NIT) loadKV(it + 2);

        const __half* base = sh + (it % 3)*ASTAGE_HALF;
        const uint2* kb = (const uint2*)base;
        const uint2* vb = (const uint2*)(base + 16384);

        // ---- S = Q K^T (log2 domain; scale folded into Q) ----
        float sc[16][4];
        #pragma unroll
        for (int jn = 0; jn < 16; jn++)
            #pragma unroll
            for (int i = 0; i < 4; i++) sc[jn][i] = 0.f;

        #pragma unroll
        for (int ks = 0; ks < 8; ks++) {
            #pragma unroll
            for (int jn = 0; jn < 16; jn++) {
                uint2 kv = kb[(ks*128 + jn*8 + gid)*4 + tig];
                mma_f16(sc[jn], qa[ks], (const uint32_t*)&kv);
            }
        }

        // ---- online softmax (base-2; quad reductions) ----
        float rmax0 = NEG_INF, rmax1 = NEG_INF;
        #pragma unroll
        for (int jn = 0; jn < 16; jn++) {
            rmax0 = fmaxf(rmax0, fmaxf(sc[jn][0], sc[jn][1]));
            rmax1 = fmaxf(rmax1, fmaxf(sc[jn][2], sc[jn][3]));
        }
        rmax0 = fmaxf(rmax0, __shfl_xor_sync(0xffffffffu, rmax0, 1));
        rmax0 = fmaxf(rmax0, __shfl_xor_sync(0xffffffffu, rmax0, 2));
        rmax1 = fmaxf(rmax1, __shfl_xor_sync(0xffffffffu, rmax1, 1));
        rmax1 = fmaxf(rmax1, __shfl_xor_sync(0xffffffffu, rmax1, 2));

        float mn0 = fmaxf(m0, rmax0), mn1 = fmaxf(m1, rmax1);
        float al0 = ex2a(m0 - mn0), al1 = ex2a(m1 - mn1);

        float rs0 = 0.f, rs1 = 0.f;
        #pragma unroll
        for (int jn = 0; jn < 16; jn++) {
            sc[jn][0] = ex2a(sc[jn][0] - mn0);
            sc[jn][1] = ex2a(sc[jn][1] - mn0);
            sc[jn][2] = ex2a(sc[jn][2] - mn1);
            sc[jn][3] = ex2a(sc[jn][3] - mn1);
            rs0 += sc[jn][0] + sc[jn][1];
            rs1 += sc[jn][2] + sc[jn][3];
        }
        rs0 += __shfl_xor_sync(0xffffffffu, rs0, 1);
        rs0 += __shfl_xor_sync(0xffffffffu, rs0, 2);
        rs1 += __shfl_xor_sync(0xffffffffu, rs1, 1);
        rs1 += __shfl_xor_sync(0xffffffffu, rs1, 2);

        l0 = l0*al0 + rs0;  l1 = l1*al1 + rs1;
        m0 = mn0;           m1 = mn1;

        #pragma unroll
        for (int jn = 0; jn < 16; jn++) {
            o[jn][0] *= al0; o[jn][1] *= al0;
            o[jn][2] *= al1; o[jn][3] *= al1;
        }

        // ---- O += P V : C-frag of S == A-frag halves of P ----
        #pragma unroll
        for (int g = 0; g < 8; g++) {
            uint32_t pa[4];
            pa[0] = f2h2(sc[2*g  ][0], sc[2*g  ][1]);
            pa[1] = f2h2(sc[2*g  ][2], sc[2*g  ][3]);
            pa[2] = f2h2(sc[2*g+1][0], sc[2*g+1][1]);
            pa[3] = f2h2(sc[2*g+1][2], sc[2*g+1][3]);
            #pragma unroll
            for (int jn = 0; jn < 16; jn++) {
                uint2 vv = vb[(g*128 + jn*8 + gid)*4 + tig];
                mma_f16(o[jn], pa, (const uint32_t*)&vv);
            }
        }
    }

    // ---- epilogue: fp16 A-fragment scatter, 4-byte paired stores ----
    float il0 = 1.f / l0, il1 = 1.f / l1;
    const int s0r = qt*128 + wid*16 + gid;
    const int m  = 2*s0r + b;
    const int mb0 = m >> 4, ml = m & 15, gA = ml & 7, rsA = ml >> 3;
    #pragma unroll
    for (int jn = 0; jn < 16; jn++) {
        int c0 = h*HDIM + jn*8 + tig*2;
        int kg = c0 >> 4, kl = c0 & 15, csA = kl >> 3, tA = (kl & 7) >> 1;
        size_t idx0 = (((size_t)mb0*KG16 + kg)*32 + gA*4 + tA)*8 + (rsA + 2*csA)*2;
        *(uint32_t*)&g_attn2h[idx0] = f2h2(o[jn][0]*il0, o[jn][1]*il0);
        *(uint32_t*)&g_attn2h[idx0 + (size_t)KG16*256]
            = f2h2(o[jn][2]*il1, o[jn][3]*il1);
    }
}

// =====================================================================
// launcher
// =====================================================================
extern "C" void kernel_launch(void* const* d_in, const int* in_sizes, int n_in,
                              void* d_out, int out_size) {
    const float* hidden = (const float*)d_in[0];
    const float* w_qkv  = (const float*)d_in[1];
    const float* w_o    = (const float*)d_in[2];
    float* out = (float*)d_out;

    cudaFuncSetAttribute(gemm_h_kernel<N_QKV,0>,
                         cudaFuncAttributeMaxDynamicSharedMemorySize, GEMM_SMEM);
    cudaFuncSetAttribute(gemm_h_kernel<DMODEL,1>,
                         cudaFuncAttributeMaxDynamicSharedMemorySize, GEMM_SMEM);
    cudaFuncSetAttribute(attn_kernel,
                         cudaFuncAttributeMaxDynamicSharedMemorySize, ATTN_SMEM);

    __half* hid2h;  cudaGetSymbolAddress((void**)&hid2h, g_hid2h);
    __half* wq2h;   cudaGetSymbolAddress((void**)&wq2h,  g_Wq2h);
    __half* wo2h;   cudaGetSymbolAddress((void**)&wo2h,  g_Wo2h);
    __half* at2h;   cudaGetSymbolAddress((void**)&at2h,  g_attn2h);

    // 0) fused prepass: all three fp32 -> fp16 packs in one launch
    pack_all_kernel<<<4096 + 6144 + 4096, 256>>>(hidden, w_qkv, w_o);

    // 1) fused QKV projection (persistent, 3 CTAs/SM), scatter epilogue
    gemm_h_kernel<N_QKV,0><<<GRID_P, 128, GEMM_SMEM>>>(hid2h, wq2h, nullptr);

    // 2) flash attention (full softmax == ring online-softmax)
    attn_kernel<<<dim3(S_LEN/128, NHQ, BATCH), 256, ATTN_SMEM>>>();

    // 3) output projection (persistent, 3 CTAs/SM)
    gemm_h_kernel<DMODEL,1><<<GRID_P, 128, GEMM_SMEM>>>(at2h, wo2h, out);
}